// round 1
// baseline (speedup 1.0000x reference)
#include <cuda_runtime.h>
#include <math.h>

#define NA 100
#define DM 256
#define HID 256
#define BATCH 64
#define NPAIR 4950
#define LDA 101
#define TILE_P 64
#define NTILES 78   // ceil(4950/64)

// Scratch (device globals; no allocation allowed)
__device__ float g_R[BATCH * NA * NA];
__device__ float g_vols[BATCH * NA];

// ---------------------------------------------------------------------------
// vols: per (b, asset) row: relu(emb @ W1 + b1) @ w2 + b2 -> softplus + 1e-6
// 16 rows per block amortize W1 traffic.
// ---------------------------------------------------------------------------
__global__ __launch_bounds__(256) void vols_kernel(
    const float* __restrict__ x, const float* __restrict__ w1,
    const float* __restrict__ b1, const float* __restrict__ w2,
    const float* __restrict__ b2) {
  int b = blockIdx.y;
  int r0 = blockIdx.x * 16;
  const float* emb = x + ((size_t)b * 64 + 63) * NA * DM;
  __shared__ float es[16][DM];
  __shared__ float red[16][8];
  int tid = threadIdx.x;
  int lane = tid & 31, warp = tid >> 5;

  for (int idx = tid; idx < 16 * DM; idx += 256) {
    int r = idx >> 8, d = idx & 255;
    es[r][d] = (r0 + r < NA) ? emb[(r0 + r) * DM + d] : 0.f;
  }
  __syncthreads();

  float acc[16];
  float bb = b1[tid];
#pragma unroll
  for (int r = 0; r < 16; r++) acc[r] = bb;

  for (int d = 0; d < DM; d++) {
    float w = w1[d * HID + tid];
#pragma unroll
    for (int r = 0; r < 16; r++) acc[r] = fmaf(es[r][d], w, acc[r]);
  }

  float wv = w2[tid];
#pragma unroll
  for (int r = 0; r < 16; r++) {
    float v = fmaxf(acc[r], 0.f) * wv;
#pragma unroll
    for (int o = 16; o; o >>= 1) v += __shfl_xor_sync(0xffffffffu, v, o);
    if (lane == 0) red[r][warp] = v;
  }
  __syncthreads();
  if (tid < 16) {
    float s = 0.f;
#pragma unroll
    for (int w = 0; w < 8; w++) s += red[tid][w];
    s += b2[0];
    // softplus, numerically stable
    float sp = fmaxf(s, 0.f) + log1pf(expf(-fabsf(s)));
    if (r0 + tid < NA) g_vols[b * NA + r0 + tid] = sp + 1e-6f;
  }
}

// ---------------------------------------------------------------------------
// pair MLP: tile of 64 pairs per block. pairvec = emb[i]*emb[j] built on the
// fly in smem; GEMM (64x256x256) with 8x8 register blocking; epilogue does
// relu-dot with w2, tanh, scatter into both triangles of g_R.
// ---------------------------------------------------------------------------
__global__ __launch_bounds__(256, 2) void pair_kernel(
    const float* __restrict__ x, const float* __restrict__ w1,
    const float* __restrict__ b1, const float* __restrict__ w2,
    const float* __restrict__ b2) {
  int b = blockIdx.y;
  int tile = blockIdx.x;
  const float* emb = x + ((size_t)b * 64 + 63) * NA * DM;

  __shared__ float As[TILE_P][17];   // 64 pairs x 16 k (padded)
  __shared__ float Bs[16][256];      // 16 k x 256 hidden
  __shared__ int si[TILE_P], sj[TILE_P];

  int tid = threadIdx.x, lane = tid & 31, warp = tid >> 5;
  int p0 = tile * TILE_P;

  if (tid < TILE_P) {
    int k = p0 + tid;
    if (k >= NPAIR) k = NPAIR - 1;  // clamp (writes skipped later)
    int i = (int)((1.0f + sqrtf(1.0f + 8.0f * (float)k)) * 0.5f);
    while ((i * (i - 1)) / 2 > k) i--;
    while (((i + 1) * i) / 2 <= k) i++;
    si[tid] = i;
    sj[tid] = k - (i * (i - 1)) / 2;
  }
  __syncthreads();

  float acc[8][8];
#pragma unroll
  for (int r = 0; r < 8; r++)
#pragma unroll
    for (int j = 0; j < 8; j++) acc[r][j] = 0.f;

  for (int k0 = 0; k0 < DM; k0 += 16) {
    // A tile: 64x16 pair-vector elements (2 gmem loads per element)
#pragma unroll
    for (int t = 0; t < 4; t++) {
      int idx = tid + t * 256;
      int r = idx >> 4, kk = idx & 15;
      As[r][kk] = emb[si[r] * DM + k0 + kk] * emb[sj[r] * DM + k0 + kk];
    }
    // B tile: 16x256 of W1, coalesced
#pragma unroll
    for (int t = 0; t < 16; t++) {
      Bs[t][tid] = w1[(k0 + t) * HID + tid];
    }
    __syncthreads();
#pragma unroll
    for (int kk = 0; kk < 16; kk++) {
      float a[8], bf[8];
#pragma unroll
      for (int r = 0; r < 8; r++) a[r] = As[warp * 8 + r][kk];
#pragma unroll
      for (int j = 0; j < 8; j++) bf[j] = Bs[kk][lane + 32 * j];
#pragma unroll
      for (int r = 0; r < 8; r++)
#pragma unroll
        for (int j = 0; j < 8; j++) acc[r][j] = fmaf(a[r], bf[j], acc[r][j]);
    }
    __syncthreads();
  }

  // epilogue: relu(h + b1) . w2 per pair row, tanh, scatter
  float bias2 = b2[0];
#pragma unroll
  for (int r = 0; r < 8; r++) {
    float partial = 0.f;
#pragma unroll
    for (int j = 0; j < 8; j++) {
      int col = lane + 32 * j;
      float h = acc[r][j] + b1[col];
      partial += fmaxf(h, 0.f) * w2[col];
    }
#pragma unroll
    for (int o = 16; o; o >>= 1) partial += __shfl_xor_sync(0xffffffffu, partial, o);
    if (lane == 0) {
      int row = warp * 8 + r;
      int k = p0 + row;
      if (k < NPAIR) {
        float t = tanhf(partial + bias2);
        int i = si[row], j = sj[row];
        g_R[(size_t)b * NA * NA + i * NA + j] = t;
        g_R[(size_t)b * NA * NA + j * NA + i] = t;
      }
    }
  }
}

// ---------------------------------------------------------------------------
// Batched parallel Jacobi eigensolver + reconstruction + epilogue.
// One block (512 threads) per batch matrix. A and V live in shared memory.
// Tournament (circle-method) ordering: 50 disjoint rotations/round, 99
// rounds/sweep. Two-phase update: A <- A*J (cols, + V <- V*J), then
// A <- J^T * A (rows). Convergence: off-diag Frobenius^2 < 1e-8.
// ---------------------------------------------------------------------------
#define EIG_THREADS 512
#define EIG_NW (EIG_THREADS / 32)
#define MAX_SWEEPS 16

__global__ __launch_bounds__(EIG_THREADS) void eig_kernel(float* __restrict__ out) {
  extern __shared__ float sm[];
  float* A   = sm;                 // NA*LDA
  float* V   = A + NA * LDA;       // NA*LDA
  float* rc  = V + NA * LDA;       // 64
  float* rs  = rc + 64;            // 64
  int*   rp  = (int*)(rs + 64);    // 64
  int*   rq  = rp + 64;            // 64
  float* sq  = (float*)(rq + 64);  // 128
  float* invs = sq + 128;          // 128
  float* red = invs + 128;         // 32

  int b = blockIdx.x;
  int tid = threadIdx.x;
  int lane = tid & 31, warp = tid >> 5;
  const float* Rg = g_R + (size_t)b * NA * NA;

  for (int idx = tid; idx < NA * NA; idx += EIG_THREADS) {
    int r = idx / NA, c = idx - r * NA;
    A[r * LDA + c] = (r == c) ? 1.0f : Rg[idx];
    V[r * LDA + c] = (r == c) ? 1.0f : 0.0f;
  }
  __syncthreads();

  for (int sweep = 0; sweep < MAX_SWEEPS; sweep++) {
    for (int round = 0; round < NA - 1; round++) {
      if (tid < NA / 2) {
        const int m = NA - 1;
        int p, q;
        if (tid == 0) { p = m; q = round % m; }
        else { p = (round + tid) % m; q = (round - tid + m) % m; }
        if (p > q) { int t = p; p = q; q = t; }
        float app = A[p * LDA + p], aqq = A[q * LDA + q], apq = A[p * LDA + q];
        float c = 1.f, s = 0.f;
        if (fabsf(apq) > 1e-12f) {
          float tau = (aqq - app) / (2.f * apq);
          float t = copysignf(1.f / (fabsf(tau) + sqrtf(1.f + tau * tau)), tau);
          c = rsqrtf(1.f + t * t);
          s = t * c;
        }
        rc[tid] = c; rs[tid] = s; rp[tid] = p; rq[tid] = q;
      }
      __syncthreads();
      // column phase: A <- A J, V <- V J
      for (int k = warp; k < NA / 2; k += EIG_NW) {
        int p = rp[k], q = rq[k];
        float c = rc[k], s = rs[k];
        for (int r = lane; r < NA; r += 32) {
          float xp = A[r * LDA + p], xq = A[r * LDA + q];
          A[r * LDA + p] = c * xp - s * xq;
          A[r * LDA + q] = s * xp + c * xq;
          float vp = V[r * LDA + p], vq = V[r * LDA + q];
          V[r * LDA + p] = c * vp - s * vq;
          V[r * LDA + q] = s * vp + c * vq;
        }
      }
      __syncthreads();
      // row phase: A <- J^T A
      for (int k = warp; k < NA / 2; k += EIG_NW) {
        int p = rp[k], q = rq[k];
        float c = rc[k], s = rs[k];
        for (int r = lane; r < NA; r += 32) {
          float xp = A[p * LDA + r], xq = A[q * LDA + r];
          A[p * LDA + r] = c * xp - s * xq;
          A[q * LDA + r] = s * xp + c * xq;
        }
      }
      __syncthreads();
    }
    // convergence check (deterministic: depends only on data)
    float part = 0.f;
    for (int idx = tid; idx < NA * NA; idx += EIG_THREADS) {
      int r = idx / NA, c = idx - r * NA;
      if (r != c) { float v = A[r * LDA + c]; part += v * v; }
    }
#pragma unroll
    for (int o = 16; o; o >>= 1) part += __shfl_xor_sync(0xffffffffu, part, o);
    if (lane == 0) red[warp] = part;
    __syncthreads();
    if (tid == 0) {
      float s = 0.f;
      for (int w = 0; w < EIG_NW; w++) s += red[w];
      red[0] = s;
    }
    __syncthreads();
    if (red[0] < 1e-8f) break;
  }

  // eigenvalues on diag; scale V columns by sqrt(clip(lambda, 1e-4))
  if (tid < NA) {
    float lam = A[tid * LDA + tid];
    sq[tid] = sqrtf(fmaxf(lam, 1e-4f));
  }
  __syncthreads();
  for (int idx = tid; idx < NA * NA; idx += EIG_THREADS) {
    int r = idx / NA, c = idx - r * NA;
    V[r * LDA + c] *= sq[c];
  }
  __syncthreads();

  // R_psd = V' V'^T into A (use symmetry)
  const int NTRI = NA * (NA + 1) / 2;
  for (int idx = tid; idx < NTRI; idx += EIG_THREADS) {
    int i = (int)((sqrtf(8.f * (float)idx + 1.f) - 1.f) * 0.5f);
    while (i * (i + 1) / 2 > idx) i--;
    while ((i + 1) * (i + 2) / 2 <= idx) i++;
    int j = idx - i * (i + 1) / 2;
    const float* vi = V + i * LDA;
    const float* vj = V + j * LDA;
    float sum = 0.f;
#pragma unroll 4
    for (int k = 0; k < NA; k++) sum = fmaf(vi[k], vj[k], sum);
    A[i * LDA + j] = sum;
    A[j * LDA + i] = sum;
  }
  __syncthreads();

  if (tid < NA) {
    float d = A[tid * LDA + tid];
    invs[tid] = rsqrtf(fmaxf(d, 1e-6f));
  }
  __syncthreads();

  float* og = out + (size_t)b * NA * NA;
  const float* vl = g_vols + b * NA;
  for (int idx = tid; idx < NA * NA; idx += EIG_THREADS) {
    int r = idx / NA, c = idx - r * NA;
    og[idx] = vl[r] * vl[c] * invs[r] * invs[c] * A[r * LDA + c];
  }
}

// ---------------------------------------------------------------------------
#define SMEM_EIG ((2 * NA * LDA + 64 + 64 + 64 + 64 + 128 + 128 + 32) * 4)

extern "C" void kernel_launch(void* const* d_in, const int* in_sizes, int n_in,
                              void* d_out, int out_size) {
  const float* x   = (const float*)d_in[0];
  const float* vw1 = (const float*)d_in[1];
  const float* vb1 = (const float*)d_in[2];
  const float* vw2 = (const float*)d_in[3];
  const float* vb2 = (const float*)d_in[4];
  const float* cw1 = (const float*)d_in[5];
  const float* cb1 = (const float*)d_in[6];
  const float* cw2 = (const float*)d_in[7];
  const float* cb2 = (const float*)d_in[8];
  float* out = (float*)d_out;

  vols_kernel<<<dim3(7, BATCH), 256>>>(x, vw1, vb1, vw2, vb2);
  pair_kernel<<<dim3(NTILES, BATCH), 256>>>(x, cw1, cb1, cw2, cb2);

  cudaFuncSetAttribute(eig_kernel, cudaFuncAttributeMaxDynamicSharedMemorySize,
                       SMEM_EIG);
  eig_kernel<<<BATCH, EIG_THREADS, SMEM_EIG>>>(out);
}

// round 6
// speedup vs baseline: 1.3074x; 1.3074x over previous
#include <cuda_runtime.h>
#include <cuda_bf16.h>
#include <math.h>
#include <stdint.h>

#define NA 100
#define DM 256
#define HID 256
#define BATCH 64
#define NPAIR 4950
#define LDA 101
#define PT 64           // pairs per CTA tile
#define PTILES 78       // ceil(4950/64)

// ---------------- device scratch (no allocation allowed) ----------------
__device__ float g_R[BATCH * NA * NA];
__device__ float g_vols[BATCH * NA];
__device__ __nv_bfloat16 g_w1t_hi[HID * DM];  // [n][k] K-major
__device__ __nv_bfloat16 g_w1t_lo[HID * DM];

__device__ __forceinline__ uint32_t smem_u32(const void* p) {
  uint32_t a;
  asm("{ .reg .u64 t; cvta.to.shared.u64 t, %1; cvt.u32.u64 %0, t; }"
      : "=r"(a) : "l"(p));
  return a;
}
__device__ __forceinline__ void ldsm_x4(uint32_t (&r)[4], uint32_t addr) {
  asm volatile(
      "ldmatrix.sync.aligned.m8n8.x4.shared.b16 {%0,%1,%2,%3}, [%4];"
      : "=r"(r[0]), "=r"(r[1]), "=r"(r[2]), "=r"(r[3]) : "r"(addr));
}
__device__ __forceinline__ void ldsm_x2(uint32_t (&r)[2], uint32_t addr) {
  asm volatile(
      "ldmatrix.sync.aligned.m8n8.x2.shared.b16 {%0,%1}, [%2];"
      : "=r"(r[0]), "=r"(r[1]) : "r"(addr));
}
__device__ __forceinline__ void mma16816(float (&d)[4], const uint32_t (&a)[4],
                                         const uint32_t (&b)[2]) {
  asm volatile(
      "mma.sync.aligned.m16n8k16.row.col.f32.bf16.bf16.f32 "
      "{%0,%1,%2,%3}, {%4,%5,%6,%7}, {%8,%9}, {%0,%1,%2,%3};"
      : "+f"(d[0]), "+f"(d[1]), "+f"(d[2]), "+f"(d[3])
      : "r"(a[0]), "r"(a[1]), "r"(a[2]), "r"(a[3]), "r"(b[0]), "r"(b[1]));
}

// ---------------------------------------------------------------------------
// W1 transpose + bf16 hi/lo split (once per launch; tiny)
// ---------------------------------------------------------------------------
__global__ void prep_w1t(const float* __restrict__ w1) {
  int n = blockIdx.x, k = threadIdx.x;
  float v = w1[k * HID + n];
  __nv_bfloat16 h = __float2bfloat16(v);
  float r = v - __bfloat162float(h);
  g_w1t_hi[n * DM + k] = h;
  g_w1t_lo[n * DM + k] = __float2bfloat16(r);
}

// ---------------------------------------------------------------------------
// vols MLP
// ---------------------------------------------------------------------------
__global__ __launch_bounds__(256) void vols_kernel(
    const float* __restrict__ x, const float* __restrict__ w1,
    const float* __restrict__ b1, const float* __restrict__ w2,
    const float* __restrict__ b2) {
  int b = blockIdx.y;
  int r0 = blockIdx.x * 16;
  const float* emb = x + ((size_t)b * 64 + 63) * NA * DM;
  __shared__ float es[16][DM];
  __shared__ float red[16][8];
  int tid = threadIdx.x;
  int lane = tid & 31, warp = tid >> 5;

  for (int idx = tid; idx < 16 * DM; idx += 256) {
    int r = idx >> 8, d = idx & 255;
    es[r][d] = (r0 + r < NA) ? emb[(r0 + r) * DM + d] : 0.f;
  }
  __syncthreads();

  float acc[16];
  float bb = b1[tid];
#pragma unroll
  for (int r = 0; r < 16; r++) acc[r] = bb;

#pragma unroll 4
  for (int d = 0; d < DM; d++) {
    float w = w1[d * HID + tid];
#pragma unroll
    for (int r = 0; r < 16; r++) acc[r] = fmaf(es[r][d], w, acc[r]);
  }

  float wv = w2[tid];
#pragma unroll
  for (int r = 0; r < 16; r++) {
    float v = fmaxf(acc[r], 0.f) * wv;
#pragma unroll
    for (int o = 16; o; o >>= 1) v += __shfl_xor_sync(0xffffffffu, v, o);
    if (lane == 0) red[r][warp] = v;
  }
  __syncthreads();
  if (tid < 16) {
    float s = 0.f;
#pragma unroll
    for (int w = 0; w < 8; w++) s += red[tid][w];
    s += b2[0];
    float sp = fmaxf(s, 0.f) + log1pf(expf(-fabsf(s)));
    if (r0 + tid < NA) g_vols[b * NA + r0 + tid] = sp + 1e-6f;
  }
}

// ---------------------------------------------------------------------------
// pair MLP via mma.sync bf16 (2-way split, 3 passes).
// CTA: 64 pairs x 256 hidden, K=256 in 8 chunks of 32. 256 threads.
// Warps: 2(M) x 4(N), warp tile 32x64. Writes g_R directly (device symbol).
// ---------------------------------------------------------------------------
#define OFF_A_HI 0                     // 64*80 = 5120
#define OFF_A_LO 5120                  // 5120
#define OFF_B_HI 10240                 // 256*80 = 20480
#define OFF_B_LO 30720                 // 20480
#define OFF_SI   51200                 // 256
#define OFF_SJ   51456                 // 256
#define OFF_B1   51712                 // 1024
#define OFF_W2   52736                 // 1024
#define OFF_RED  53760                 // 64*4*4 = 1024
#define SMEM_PAIR 54784

__global__ __launch_bounds__(256) void pair_mma_kernel(
    const float* __restrict__ x, const float* __restrict__ b1,
    const float* __restrict__ w2, const float* __restrict__ b2) {
  extern __shared__ char smem[];
  uint32_t sb = smem_u32(smem);
  int b = blockIdx.y, tile = blockIdx.x;
  int tid = threadIdx.x, lane = tid & 31, warp = tid >> 5;
  int wm = warp >> 2, wn = warp & 3;   // 2 x 4 warps
  const float* emb = x + ((size_t)b * 64 + 63) * NA * DM;

  int* si = (int*)(smem + OFF_SI);
  int* sj = (int*)(smem + OFF_SJ);
  float* b1s = (float*)(smem + OFF_B1);
  float* w2s = (float*)(smem + OFF_W2);
  float* red = (float*)(smem + OFF_RED);

  if (tid < PT) {
    int k = tile * PT + tid;
    if (k >= NPAIR) k = NPAIR - 1;
    int i = (int)((1.0f + sqrtf(1.0f + 8.0f * (float)k)) * 0.5f);
    while ((i * (i - 1)) / 2 > k) i--;
    while (((i + 1) * i) / 2 <= k) i++;
    si[tid] = i;
    sj[tid] = k - (i * (i - 1)) / 2;
  }
  b1s[tid] = b1[tid];
  w2s[tid] = w2[tid];
  __syncthreads();

  float acc[2][8][4];
#pragma unroll
  for (int mt = 0; mt < 2; mt++)
#pragma unroll
    for (int nt = 0; nt < 8; nt++)
#pragma unroll
      for (int e = 0; e < 4; e++) acc[mt][nt][e] = 0.f;

  for (int ch = 0; ch < 8; ch++) {
    int k0 = ch * 32;
    // A: 64x32 pair products, hi/lo split (1024 float2 -> 4 iters)
#pragma unroll
    for (int t = 0; t < 4; t++) {
      int idx = tid + t * 256;
      int row = idx >> 4, kk2 = idx & 15;
      const float2 ea = *(const float2*)(emb + si[row] * DM + k0 + 2 * kk2);
      const float2 eb = *(const float2*)(emb + sj[row] * DM + k0 + 2 * kk2);
      float p0 = ea.x * eb.x, p1 = ea.y * eb.y;
      __nv_bfloat16 h0 = __float2bfloat16(p0);
      __nv_bfloat16 h1 = __float2bfloat16(p1);
      __nv_bfloat16 l0 = __float2bfloat16(p0 - __bfloat162float(h0));
      __nv_bfloat16 l1 = __float2bfloat16(p1 - __bfloat162float(h1));
      uint32_t hp = ((uint32_t)*(uint16_t*)&h1 << 16) | *(uint16_t*)&h0;
      uint32_t lp = ((uint32_t)*(uint16_t*)&l1 << 16) | *(uint16_t*)&l0;
      *(uint32_t*)(smem + OFF_A_HI + row * 80 + kk2 * 4) = hp;
      *(uint32_t*)(smem + OFF_A_LO + row * 80 + kk2 * 4) = lp;
    }
    // B: 256x32 of pre-split W1^T (1024 uint4 -> 4 iters)
#pragma unroll
    for (int t = 0; t < 4; t++) {
      int idx = tid + t * 256;
      int n = idx >> 2, kg = idx & 3;
      uint4 hv = *(const uint4*)(g_w1t_hi + n * DM + k0 + kg * 8);
      uint4 lv = *(const uint4*)(g_w1t_lo + n * DM + k0 + kg * 8);
      *(uint4*)(smem + OFF_B_HI + n * 80 + kg * 16) = hv;
      *(uint4*)(smem + OFF_B_LO + n * 80 + kg * 16) = lv;
    }
    __syncthreads();

#pragma unroll
    for (int ks = 0; ks < 2; ks++) {
      uint32_t ah[2][4], al[2][4], bb[8][2];
      int arow = (lane & 7) + ((lane >> 3) & 1) * 8;
      int acolb = ks * 32 + ((lane >> 4) << 4);
#pragma unroll
      for (int mt = 0; mt < 2; mt++) {
        uint32_t ra = (uint32_t)((wm * 32 + mt * 16 + arow) * 80 + acolb);
        ldsm_x4(ah[mt], sb + OFF_A_HI + ra);
        ldsm_x4(al[mt], sb + OFF_A_LO + ra);
      }
      int bl_ = lane & 15;
      int brow = bl_ & 7;
      int bcolb = ks * 32 + ((bl_ >> 3) << 4);
#pragma unroll
      for (int nt = 0; nt < 8; nt++) {
        uint32_t rb = (uint32_t)((wn * 64 + nt * 8 + brow) * 80 + bcolb);
        ldsm_x2(bb[nt], sb + OFF_B_HI + rb);
      }
      // pass 1: a_hi*b_hi ; pass 2: a_lo*b_hi
#pragma unroll
      for (int mt = 0; mt < 2; mt++)
#pragma unroll
        for (int nt = 0; nt < 8; nt++) mma16816(acc[mt][nt], ah[mt], bb[nt]);
#pragma unroll
      for (int mt = 0; mt < 2; mt++)
#pragma unroll
        for (int nt = 0; nt < 8; nt++) mma16816(acc[mt][nt], al[mt], bb[nt]);
      // pass 3: a_hi*b_lo (reuse bb regs)
#pragma unroll
      for (int nt = 0; nt < 8; nt++) {
        uint32_t rb = (uint32_t)((wn * 64 + nt * 8 + brow) * 80 + bcolb);
        ldsm_x2(bb[nt], sb + OFF_B_LO + rb);
      }
#pragma unroll
      for (int mt = 0; mt < 2; mt++)
#pragma unroll
        for (int nt = 0; nt < 8; nt++) mma16816(acc[mt][nt], ah[mt], bb[nt]);
    }
    __syncthreads();
  }

  // Epilogue: relu(h + b1) . w2, quad shuffle-reduce, cross-warp reduce
#pragma unroll
  for (int mt = 0; mt < 2; mt++) {
#pragma unroll
    for (int half = 0; half < 2; half++) {
      float s = 0.f;
#pragma unroll
      for (int nt = 0; nt < 8; nt++) {
        int col = wn * 64 + nt * 8 + 2 * (lane & 3);
        float h0 = acc[mt][nt][half * 2 + 0] + b1s[col];
        float h1 = acc[mt][nt][half * 2 + 1] + b1s[col + 1];
        s = fmaf(fmaxf(h0, 0.f), w2s[col], s);
        s = fmaf(fmaxf(h1, 0.f), w2s[col + 1], s);
      }
      s += __shfl_xor_sync(0xffffffffu, s, 1);
      s += __shfl_xor_sync(0xffffffffu, s, 2);
      if ((lane & 3) == 0) {
        int row = wm * 32 + mt * 16 + half * 8 + (lane >> 2);
        red[row * 4 + wn] = s;
      }
    }
  }
  __syncthreads();
  if (tid < PT) {
    int k = tile * PT + tid;
    if (k < NPAIR) {
      float s = red[tid * 4] + red[tid * 4 + 1] + red[tid * 4 + 2] +
                red[tid * 4 + 3] + b2[0];
      float t = tanhf(s);
      int i = si[tid], j = sj[tid];
      g_R[(size_t)b * NA * NA + i * NA + j] = t;
      g_R[(size_t)b * NA * NA + j * NA + i] = t;
    }
  }
}

// ---------------------------------------------------------------------------
// Batched parallel Jacobi eig + reconstruction + epilogue (rotation-skip).
// ---------------------------------------------------------------------------
#define EIG_THREADS 512
#define EIG_NW (EIG_THREADS / 32)
#define MAX_SWEEPS 16

__global__ __launch_bounds__(EIG_THREADS) void eig_kernel(float* __restrict__ out) {
  extern __shared__ float sm[];
  float* A = sm;
  float* V = A + NA * LDA;
  float* rc = V + NA * LDA;
  float* rs = rc + 64;
  int* rp = (int*)(rs + 64);
  int* rq = rp + 64;
  float* sq = (float*)(rq + 64);
  float* invs = sq + 128;
  float* red = invs + 128;

  int b = blockIdx.x;
  int tid = threadIdx.x;
  int lane = tid & 31, warp = tid >> 5;
  const float* Rg = g_R + (size_t)b * NA * NA;

  for (int idx = tid; idx < NA * NA; idx += EIG_THREADS) {
    int r = idx / NA, c = idx - r * NA;
    A[r * LDA + c] = (r == c) ? 1.0f : Rg[idx];
    V[r * LDA + c] = (r == c) ? 1.0f : 0.0f;
  }
  __syncthreads();

  for (int sweep = 0; sweep < MAX_SWEEPS; sweep++) {
    for (int round = 0; round < NA - 1; round++) {
      if (tid < NA / 2) {
        const int m = NA - 1;
        int p, q;
        if (tid == 0) { p = m; q = round % m; }
        else { p = (round + tid) % m; q = (round - tid + m) % m; }
        if (p > q) { int t = p; p = q; q = t; }
        float app = A[p * LDA + p], aqq = A[q * LDA + q], apq = A[p * LDA + q];
        float c = 1.f, s = 0.f;
        if (fabsf(apq) > 1e-7f) {
          float tau = (aqq - app) / (2.f * apq);
          float t = copysignf(1.f / (fabsf(tau) + sqrtf(1.f + tau * tau)), tau);
          c = rsqrtf(1.f + t * t);
          s = t * c;
        }
        rc[tid] = c; rs[tid] = s; rp[tid] = p; rq[tid] = q;
      }
      __syncthreads();
      for (int k = warp; k < NA / 2; k += EIG_NW) {
        float s = rs[k];
        if (s == 0.f) continue;
        int p = rp[k], q = rq[k];
        float c = rc[k];
        for (int r = lane; r < NA; r += 32) {
          float xp = A[r * LDA + p], xq = A[r * LDA + q];
          A[r * LDA + p] = c * xp - s * xq;
          A[r * LDA + q] = s * xp + c * xq;
          float vp = V[r * LDA + p], vq = V[r * LDA + q];
          V[r * LDA + p] = c * vp - s * vq;
          V[r * LDA + q] = s * vp + c * vq;
        }
      }
      __syncthreads();
      for (int k = warp; k < NA / 2; k += EIG_NW) {
        float s = rs[k];
        if (s == 0.f) continue;
        int p = rp[k], q = rq[k];
        float c = rc[k];
        for (int r = lane; r < NA; r += 32) {
          float xp = A[p * LDA + r], xq = A[q * LDA + r];
          A[p * LDA + r] = c * xp - s * xq;
          A[q * LDA + r] = s * xp + c * xq;
        }
      }
      __syncthreads();
    }
    float part = 0.f;
    for (int idx = tid; idx < NA * NA; idx += EIG_THREADS) {
      int r = idx / NA, c = idx - r * NA;
      if (r != c) { float v = A[r * LDA + c]; part += v * v; }
    }
#pragma unroll
    for (int o = 16; o; o >>= 1) part += __shfl_xor_sync(0xffffffffu, part, o);
    if (lane == 0) red[warp] = part;
    __syncthreads();
    if (tid == 0) {
      float s = 0.f;
      for (int w = 0; w < EIG_NW; w++) s += red[w];
      red[0] = s;
    }
    __syncthreads();
    if (red[0] < 1e-8f) break;
  }

  if (tid < NA) {
    float lam = A[tid * LDA + tid];
    sq[tid] = sqrtf(fmaxf(lam, 1e-4f));
  }
  __syncthreads();
  for (int idx = tid; idx < NA * NA; idx += EIG_THREADS) {
    int r = idx / NA, c = idx - r * NA;
    V[r * LDA + c] *= sq[c];
  }
  __syncthreads();

  const int NTRI = NA * (NA + 1) / 2;
  for (int idx = tid; idx < NTRI; idx += EIG_THREADS) {
    int i = (int)((sqrtf(8.f * (float)idx + 1.f) - 1.f) * 0.5f);
    while (i * (i + 1) / 2 > idx) i--;
    while ((i + 1) * (i + 2) / 2 <= idx) i++;
    int j = idx - i * (i + 1) / 2;
    const float* vi = V + i * LDA;
    const float* vj = V + j * LDA;
    float sum = 0.f;
#pragma unroll 4
    for (int k = 0; k < NA; k++) sum = fmaf(vi[k], vj[k], sum);
    A[i * LDA + j] = sum;
    A[j * LDA + i] = sum;
  }
  __syncthreads();

  if (tid < NA) {
    float d = A[tid * LDA + tid];
    invs[tid] = rsqrtf(fmaxf(d, 1e-6f));
  }
  __syncthreads();

  float* og = out + (size_t)b * NA * NA;
  const float* vl = g_vols + b * NA;
  for (int idx = tid; idx < NA * NA; idx += EIG_THREADS) {
    int r = idx / NA, c = idx - r * NA;
    og[idx] = vl[r] * vl[c] * invs[r] * invs[c] * A[r * LDA + c];
  }
}

#define SMEM_EIG ((2 * NA * LDA + 64 + 64 + 64 + 64 + 128 + 128 + 32) * 4)

extern "C" void kernel_launch(void* const* d_in, const int* in_sizes, int n_in,
                              void* d_out, int out_size) {
  const float* x   = (const float*)d_in[0];
  const float* vw1 = (const float*)d_in[1];
  const float* vb1 = (const float*)d_in[2];
  const float* vw2 = (const float*)d_in[3];
  const float* vb2 = (const float*)d_in[4];
  const float* cw1 = (const float*)d_in[5];
  const float* cb1 = (const float*)d_in[6];
  const float* cw2 = (const float*)d_in[7];
  const float* cb2 = (const float*)d_in[8];
  float* out = (float*)d_out;

  prep_w1t<<<HID, DM>>>(cw1);
  vols_kernel<<<dim3(7, BATCH), 256>>>(x, vw1, vb1, vw2, vb2);

  cudaFuncSetAttribute(pair_mma_kernel,
                       cudaFuncAttributeMaxDynamicSharedMemorySize, SMEM_PAIR);
  pair_mma_kernel<<<dim3(PTILES, BATCH), 256, SMEM_PAIR>>>(x, cb1, cw2, cb2);

  cudaFuncSetAttribute(eig_kernel, cudaFuncAttributeMaxDynamicSharedMemorySize,
                       SMEM_EIG);
  eig_kernel<<<BATCH, EIG_THREADS, SMEM_EIG>>>(out);
}